// round 10
// baseline (speedup 1.0000x reference)
#include <cuda_runtime.h>

#define NNODE 5632          // nodes per graph (L+G+F)
#define BATCH 64
#define HDIM  64
#define NTOT  360448        // NNODE*BATCH
#define EGE   16384         // edges per graph (shared topology)
#define NL    2048
#define NG    512
#define NF    3072
#define ROWF  4096          // BATCH*HDIM floats per node row
#define NLAYER 4

typedef unsigned long long u64;

// ---------------- device scratch (static: no runtime allocation) -------------
__device__ float g_bufA[23068672];   // 92.3 MB  h ping
__device__ float g_bufB[23068672];   // 92.3 MB  h pong / z
__device__ float g_bufY[23068672];   // 92.3 MB  y = hn @ Wrel^T
__device__ float g_wcat[NLAYER * HDIM * 128];  // transposed [layer][k][j] weights
__device__ int   g_deg[NNODE];
__device__ int   g_rowptr[NNODE + 1];
__device__ int   g_fill[NNODE];
__device__ int   g_col[EGE];

// ---------------- packed fp32x2 helpers (Blackwell FFMA2 path) ---------------
__device__ __forceinline__ u64 pk2(float lo, float hi) {
    u64 r; asm("mov.b64 %0,{%1,%2};" : "=l"(r) : "f"(lo), "f"(hi)); return r;
}
__device__ __forceinline__ void upk2(u64 v, float &lo, float &hi) {
    asm("mov.b64 {%0,%1},%2;" : "=f"(lo), "=f"(hi) : "l"(v));
}
__device__ __forceinline__ void fma2(u64 &acc, u64 a, u64 b) {
    asm("fma.rn.f32x2 %0,%1,%2,%0;" : "+l"(acc) : "l"(a), "l"(b));
}

// ---------------- weight prep: Wcat[layer][k][j] (j<64: Wrel, else Wroot) ----
__global__ void k_wprep(const float* __restrict__ wr, const float* __restrict__ wo) {
    int idx = blockIdx.x * 256 + threadIdx.x;
    if (idx >= NLAYER * 64 * 128) return;
    int i = idx >> 13;          // layer
    int rem = idx & 8191;
    int k = rem >> 7;
    int j = rem & 127;
    float v = (j < 64) ? wr[i * 4096 + j * 64 + k]
                       : wo[i * 4096 + (j - 64) * 64 + k];
    g_wcat[idx] = v;
}

// ---------------- CSR build over the shared local topology -------------------
__global__ void k_zero() {
    int i = blockIdx.x * 256 + threadIdx.x;
    if (i < NNODE) g_deg[i] = 0;
}
__global__ void k_hist(const int* __restrict__ dst) {
    int e = blockIdx.x * 256 + threadIdx.x;
    if (e < EGE) atomicAdd(&g_deg[dst[e]], 1);
}
__global__ void k_scan() {   // single block, 1024 threads
    __shared__ int sm[1024];
    int t = threadIdx.x;
    int base = t * 6;
    int v[6]; int s = 0;
#pragma unroll
    for (int i = 0; i < 6; i++) {
        int id = base + i;
        int d = (id < NNODE) ? g_deg[id] : 0;
        v[i] = d; s += d;
    }
    sm[t] = s; __syncthreads();
    for (int off = 1; off < 1024; off <<= 1) {
        int add = (t >= off) ? sm[t - off] : 0;
        __syncthreads();
        sm[t] += add;
        __syncthreads();
    }
    int run = sm[t] - s;
#pragma unroll
    for (int i = 0; i < 6; i++) {
        int id = base + i;
        if (id < NNODE) { g_rowptr[id] = run; g_fill[id] = run; run += v[i]; }
    }
    if (t == 1023) g_rowptr[NNODE] = sm[1023];
}
__global__ void k_fill(const int* __restrict__ src, const int* __restrict__ dst) {
    int e = blockIdx.x * 256 + threadIdx.x;
    if (e < EGE) {
        int p = atomicAdd(&g_fill[dst[e]], 1);
        g_col[p] = src[e];
    }
}

// ---------------- encoder: h[n*B+b][:] = relu(x[b*N+n] @ encW^T + b) ---------
__global__ void k_encoder(const float* __restrict__ x,
                          const float* __restrict__ ew,
                          const float* __restrict__ eb) {
    int gw = blockIdx.x * 8 + (threadIdx.x >> 5);   // one warp per (n,b) row
    int lane = threadIdx.x & 31;
    int n = gw / BATCH, b = gw % BATCH;
    size_t gn = (size_t)b * NNODE + n;
    float xv = (lane < 7) ? x[gn * 7 + lane] : 0.f;
    float a0 = eb[lane], a1 = eb[lane + 32];
#pragma unroll
    for (int k = 0; k < 7; k++) {
        float xk = __shfl_sync(0xffffffffu, xv, k);
        a0 = fmaf(xk, ew[lane * 7 + k], a0);
        a1 = fmaf(xk, ew[(lane + 32) * 7 + k], a1);
    }
    size_t r = (size_t)gw * 64;
    g_bufA[r + lane]      = fmaxf(a0, 0.f);
    g_bufA[r + lane + 32] = fmaxf(a1, 0.f);
}

// ---------------- Pass A: fused LayerNorm + dual GEMM (y, z) -----------------
// block = 128 threads, 128 rows; thread (c = t&7, rg = t>>3) computes
// 8 rows x 8 output-pairs via packed fp32x2 FMA.
__global__ void __launch_bounds__(128) k_passA(const float* __restrict__ lng,
                                               const float* __restrict__ lnb,
                                               const float* __restrict__ brel,
                                               int layer, int sel) {
    const float* in  = sel ? g_bufB : g_bufA;
    float*       zout = sel ? g_bufA : g_bufB;
    __shared__ float rs[128 * 65];
    __shared__ float sg[64], sb[64];
    int t = threadIdx.x;
    if (t < 64) { sg[t] = lng[t]; sb[t] = lnb[t]; }

    // coalesced load of 128 rows x 64 floats into padded smem
    size_t base = (size_t)blockIdx.x * (128 * 64);
    const float4* gin = (const float4*)(in + base);
#pragma unroll
    for (int i = 0; i < 16; i++) {
        int f4 = t + i * 128;
        float4 v = gin[f4];
        int row = f4 >> 4;
        int k = (f4 & 15) << 2;
        float* dptr = &rs[row * 65 + k];
        dptr[0] = v.x; dptr[1] = v.y; dptr[2] = v.z; dptr[3] = v.w;
    }
    __syncthreads();

    // LayerNorm: thread t owns row t (conflict-free: bank = (t+k)&31)
    {
        float s1 = 0.f, s2 = 0.f;
#pragma unroll
        for (int k = 0; k < 64; k++) { float v = rs[t * 65 + k]; s1 += v; s2 += v * v; }
        float mu = s1 * (1.f / 64.f);
        float var = s2 * (1.f / 64.f) - mu * mu;
        float r = rsqrtf(var + 1e-5f);
#pragma unroll
        for (int k = 0; k < 64; k++) {
            float v = rs[t * 65 + k];
            rs[t * 65 + k] = (v - mu) * r * sg[k] + sb[k];
        }
    }
    __syncthreads();

    int c = t & 7, rg = t >> 3;
    const u64* wb = ((const u64*)g_wcat) + layer * 4096 + c;
    u64 acc[8][8];
#pragma unroll
    for (int a = 0; a < 8; a++)
#pragma unroll
        for (int b = 0; b < 8; b++) acc[a][b] = 0ull;

    const float* arow = &rs[rg * 8 * 65];
#pragma unroll 4
    for (int k = 0; k < 64; k++) {
        u64 a2[8];
#pragma unroll
        for (int rr = 0; rr < 8; rr++) {
            float av = arow[rr * 65 + k];
            a2[rr] = pk2(av, av);
        }
        u64 w2[8];
#pragma unroll
        for (int p = 0; p < 8; p++) w2[p] = wb[k * 64 + 8 * p];
#pragma unroll
        for (int rr = 0; rr < 8; rr++)
#pragma unroll
            for (int p = 0; p < 8; p++) fma2(acc[rr][p], a2[rr], w2[p]);
    }

    // epilogue: p<4 -> y outputs, p>=4 -> z outputs (+ b_rel)
    size_t rowbase = (size_t)blockIdx.x * 128 + rg * 8;
#pragma unroll
    for (int rr = 0; rr < 8; rr++) {
        size_t row = rowbase + rr;
#pragma unroll
        for (int p = 0; p < 8; p++) {
            int j0 = 2 * (c + 8 * p);
            float lo, hi; upk2(acc[rr][p], lo, hi);
            if (p < 4) {
                *reinterpret_cast<float2*>(&g_bufY[row * 64 + j0]) = make_float2(lo, hi);
            } else {
                int jj = j0 - 64;
                lo += brel[layer * 64 + jj];
                hi += brel[layer * 64 + jj + 1];
                *reinterpret_cast<float2*>(&zout[row * 64 + jj]) = make_float2(lo, hi);
            }
        }
    }
}

// ---------------- Pass B: h'[d] = relu( sum_{s in in(d)} y[s] + z[d] ) -------
__global__ void k_passB(int sel) {
    float* hb = sel ? g_bufA : g_bufB;     // same buffer passA wrote z into
    int d = blockIdx.y;
    int off = blockIdx.x * 1024 + threadIdx.x * 4;
    size_t zi = (size_t)d * ROWF + off;
    float4 acc = *reinterpret_cast<const float4*>(&hb[zi]);
    int beg = g_rowptr[d], end = g_rowptr[d + 1];
    for (int e = beg; e < end; e++) {
        int s = g_col[e];
        float4 v = *reinterpret_cast<const float4*>(&g_bufY[(size_t)s * ROWF + off]);
        acc.x += v.x; acc.y += v.y; acc.z += v.z; acc.w += v.w;
    }
    acc.x = fmaxf(acc.x, 0.f); acc.y = fmaxf(acc.y, 0.f);
    acc.z = fmaxf(acc.z, 0.f); acc.w = fmaxf(acc.w, 0.f);
    *reinterpret_cast<float4*>(&hb[zi]) = acc;
}

// ---------------- readout (p / f): warp-per-output dot of 64 -----------------
__global__ void k_readout(const int* __restrict__ idx, const float* __restrict__ w,
                          const float* __restrict__ bias, float* __restrict__ out,
                          int cnt) {
    int gw = blockIdx.x * 8 + (threadIdx.x >> 5);
    int lane = threadIdx.x & 31;
    if (gw >= cnt) return;
    int gi = idx[gw];
    int n = gi % NNODE;
    int b = gi / NNODE;
    size_t row = ((size_t)n * BATCH + b) * 64;
    float s = g_bufA[row + lane] * w[lane] + g_bufA[row + lane + 32] * w[lane + 32];
#pragma unroll
    for (int o = 16; o > 0; o >>= 1) s += __shfl_xor_sync(0xffffffffu, s, o);
    if (lane == 0) out[gw] = s + bias[0];
}

// ---------------- md = demand - (p @ gm^T + f @ lm^T) via sparse scatter -----
__global__ void k_mdinit(const float* __restrict__ x, const int* __restrict__ loc,
                         float* __restrict__ md) {
    int i = blockIdx.x * 256 + threadIdx.x;
    if (i < BATCH * NL) md[i] = x[(size_t)loc[i] * 7];   // feature 0 = demand
}
__global__ void k_mdscatter(const float* __restrict__ gm, const float* __restrict__ lm,
                            const float* __restrict__ p, const float* __restrict__ f,
                            float* __restrict__ md) {
    int idx = blockIdx.x * 256 + threadIdx.x;
    const int TG = NL * NG;
    if (idx < TG) {
        float v = gm[idx];
        if (v != 0.f) {
            int l = idx / NG, g = idx % NG;
            for (int b = 0; b < BATCH; b++)
                atomicAdd(&md[b * NL + l], -v * p[b * NG + g]);
        }
    } else {
        int j = idx - TG;
        if (j >= NL * NF) return;
        float v = lm[j];
        if (v != 0.f) {
            int l = j / NF, fi = j % NF;
            for (int b = 0; b < BATCH; b++)
                atomicAdd(&md[b * NL + l], -v * f[b * NF + fi]);
        }
    }
}

// -----------------------------------------------------------------------------
extern "C" void kernel_launch(void* const* d_in, const int* in_sizes, int n_in,
                              void* d_out, int out_size) {
    const float* x        = (const float*)d_in[0];
    const int*   edge     = (const int*)  d_in[1];
    const int*   prod_idx = (const int*)  d_in[2];
    const int*   line_idx = (const int*)  d_in[3];
    const int*   loc_idx  = (const int*)  d_in[4];
    const float* enc_w    = (const float*)d_in[5];
    const float* enc_b    = (const float*)d_in[6];
    const float* ln_g     = (const float*)d_in[7];
    const float* ln_b     = (const float*)d_in[8];
    const float* w_rel    = (const float*)d_in[9];
    const float* b_rel    = (const float*)d_in[10];
    const float* w_root   = (const float*)d_in[11];
    const float* prod_w   = (const float*)d_in[12];
    const float* prod_b   = (const float*)d_in[13];
    const float* flow_w   = (const float*)d_in[14];
    const float* flow_b   = (const float*)d_in[15];
    const float* gm       = (const float*)d_in[16];
    const float* lm       = (const float*)d_in[17];

    float* out   = (float*)d_out;
    float* p_out = out;                       // [B,G]  = 32768
    float* f_out = out + 32768;               // [B,F]  = 196608
    float* md    = out + 32768 + 196608;      // [B,L]  = 131072

    const int E = 1048576;                    // B * EG
    const int* src = edge;                    // local topology = first EG entries (b=0)
    const int* dst = edge + E;

    k_wprep<<<128, 256>>>(w_rel, w_root);
    k_zero<<<22, 256>>>();
    k_hist<<<64, 256>>>(dst);
    k_scan<<<1, 1024>>>();
    k_fill<<<64, 256>>>(src, dst);

    k_encoder<<<45056, 256>>>(x, enc_w, enc_b);   // 45056*8 = NTOT warps

    for (int i = 0; i < NLAYER; i++) {
        k_passA<<<2816, 128>>>(ln_g, ln_b, b_rel, i, i & 1);   // NTOT/128 blocks
        k_passB<<<dim3(4, NNODE), 256>>>(i & 1);
    }
    // final h lives in g_bufA after 4 layers

    k_readout<<<4096, 256>>>(prod_idx, prod_w, prod_b, p_out, 32768);
    k_readout<<<24576, 256>>>(line_idx, flow_w, flow_b, f_out, 196608);
    k_mdinit<<<512, 256>>>(x, loc_idx, md);
    k_mdscatter<<<28672, 256>>>(gm, lm, p_out, f_out, md);
}

// round 11
// speedup vs baseline: 1.1679x; 1.1679x over previous
#include <cuda_runtime.h>

#define NNODE 5632          // nodes per graph (L+G+F)
#define BATCH 64
#define HDIM  64
#define NTOT  360448        // NNODE*BATCH
#define EGE   16384         // edges per graph (shared topology)
#define NL    2048
#define NG    512
#define NF    3072
#define ROWF  4096          // BATCH*HDIM floats per node row
#define NLAYER 4

typedef unsigned long long u64;

// ---------------- device scratch (static: no runtime allocation) -------------
__device__ float g_yA[23068672];   // 92.3 MB
__device__ float g_zA[23068672];
__device__ float g_yB[23068672];
__device__ float g_zB[23068672];
__device__ float g_wcat[NLAYER * HDIM * 128];  // [layer][k][j] (j<64 Wrel, else Wroot)
__device__ int   g_deg[NNODE];
__device__ int   g_rowptr[NNODE + 1];
__device__ int   g_fill[NNODE];
__device__ int   g_col[EGE];

// ---------------- packed fp32x2 helpers (Blackwell FFMA2 path) ---------------
__device__ __forceinline__ u64 pk2(float lo, float hi) {
    u64 r; asm("mov.b64 %0,{%1,%2};" : "=l"(r) : "f"(lo), "f"(hi)); return r;
}
__device__ __forceinline__ void upk2(u64 v, float &lo, float &hi) {
    asm("mov.b64 {%0,%1},%2;" : "=f"(lo), "=f"(hi) : "l"(v));
}
__device__ __forceinline__ void fma2(u64 &acc, u64 a, u64 b) {
    asm("fma.rn.f32x2 %0,%1,%2,%0;" : "+l"(acc) : "l"(a), "l"(b));
}

// ---------------- weight prep: Wcat[layer][k][j] -----------------------------
__global__ void k_wprep(const float* __restrict__ wr, const float* __restrict__ wo) {
    int idx = blockIdx.x * 256 + threadIdx.x;
    if (idx >= NLAYER * 64 * 128) return;
    int i = idx >> 13;          // layer
    int rem = idx & 8191;
    int k = rem >> 7;
    int j = rem & 127;
    float v = (j < 64) ? wr[i * 4096 + j * 64 + k]
                       : wo[i * 4096 + (j - 64) * 64 + k];
    g_wcat[idx] = v;
}

// ---------------- CSR build over the shared local topology -------------------
__global__ void k_zero() {
    int i = blockIdx.x * 256 + threadIdx.x;
    if (i < NNODE) g_deg[i] = 0;
}
__global__ void k_hist(const int* __restrict__ dst) {
    int e = blockIdx.x * 256 + threadIdx.x;
    if (e < EGE) atomicAdd(&g_deg[dst[e]], 1);
}
__global__ void k_scan() {   // single block, 1024 threads
    __shared__ int sm[1024];
    int t = threadIdx.x;
    int base = t * 6;
    int v[6]; int s = 0;
#pragma unroll
    for (int i = 0; i < 6; i++) {
        int id = base + i;
        int d = (id < NNODE) ? g_deg[id] : 0;
        v[i] = d; s += d;
    }
    sm[t] = s; __syncthreads();
    for (int off = 1; off < 1024; off <<= 1) {
        int add = (t >= off) ? sm[t - off] : 0;
        __syncthreads();
        sm[t] += add;
        __syncthreads();
    }
    int run = sm[t] - s;
#pragma unroll
    for (int i = 0; i < 6; i++) {
        int id = base + i;
        if (id < NNODE) { g_rowptr[id] = run; g_fill[id] = run; run += v[i]; }
    }
    if (t == 1023) g_rowptr[NNODE] = sm[1023];
}
__global__ void k_fill(const int* __restrict__ src, const int* __restrict__ dst) {
    int e = blockIdx.x * 256 + threadIdx.x;
    if (e < EGE) {
        int p = atomicAdd(&g_fill[dst[e]], 1);
        g_col[p] = src[e];
    }
}

// ---------------- fused layer kernel -----------------------------------------
// Block = 2 nodes (128 rows of [B,H]-major state), 256 threads.
// Phase 1: h = relu(gather(y_in) + z_in)   (layer 0: h = relu(x @ encW^T + b))
// Phase 2: LayerNorm(h) in smem
// Phase 3: dual GEMM: y_out = hn @ Wrel^T ; z_out = hn @ Wroot^T + b_rel
__global__ void __launch_bounds__(256, 2) k_layer(
    const float* __restrict__ lng, const float* __restrict__ lnb,
    const float* __restrict__ brel,
    const float* __restrict__ x,  const float* __restrict__ ew,
    const float* __restrict__ eb, int layer)
{
    const float* yin; const float* zin; float* yout; float* zout;
    if (layer & 1) { yin = g_yA; zin = g_zA; yout = g_yB; zout = g_zB; }
    else           { yin = g_yB; zin = g_zB; yout = g_yA; zout = g_zA; }

    __shared__ float rs[128 * 65];
    __shared__ float sg[64], sb[64];
    int t = threadIdx.x;
    if (t < 64) { sg[t] = lng[t]; sb[t] = lnb[t]; }
    int blk = blockIdx.x;

    if (layer == 0) {
        // encoder path: thread t<128 owns row t (node, batch)
        if (t < 128) {
            int n = blk * 2 + (t >> 6);
            int b = t & 63;
            const float* xr = x + ((size_t)b * NNODE + n) * 7;
            float xv[7];
#pragma unroll
            for (int j = 0; j < 7; j++) xv[j] = xr[j];
#pragma unroll
            for (int k = 0; k < 64; k++) {
                float a = eb[k];
#pragma unroll
                for (int j = 0; j < 7; j++) a = fmaf(xv[j], ew[k * 7 + j], a);
                rs[t * 65 + k] = fmaxf(a, 0.f);
            }
        }
    } else {
        int nh = t >> 7, tt = t & 127;
        int d = blk * 2 + nh;
        size_t base = (size_t)d * ROWF + tt * 32;
        float4 acc[8];
#pragma unroll
        for (int q = 0; q < 8; q++)
            acc[q] = *reinterpret_cast<const float4*>(zin + base + q * 4);
        int beg = g_rowptr[d], end = g_rowptr[d + 1];
        for (int e = beg; e < end; e++) {
            int s = g_col[e];
            const float* yr = yin + (size_t)s * ROWF + tt * 32;
#pragma unroll
            for (int q = 0; q < 8; q++) {
                float4 v = *reinterpret_cast<const float4*>(yr + q * 4);
                acc[q].x += v.x; acc[q].y += v.y; acc[q].z += v.z; acc[q].w += v.w;
            }
        }
        // relu + deposit into padded smem: row = nh*64 + tt/2, k base = (tt&1)*32
        int row = nh * 64 + (tt >> 1);
        int kb = (tt & 1) * 32;
        float* dp = &rs[row * 65 + kb];
#pragma unroll
        for (int q = 0; q < 8; q++) {
            dp[q * 4 + 0] = fmaxf(acc[q].x, 0.f);
            dp[q * 4 + 1] = fmaxf(acc[q].y, 0.f);
            dp[q * 4 + 2] = fmaxf(acc[q].z, 0.f);
            dp[q * 4 + 3] = fmaxf(acc[q].w, 0.f);
        }
    }
    __syncthreads();

    // LayerNorm: thread t<128 owns row t (conflict-free: bank = (t+k)&31)
    if (t < 128) {
        float s1 = 0.f, s2 = 0.f;
#pragma unroll
        for (int k = 0; k < 64; k++) { float v = rs[t * 65 + k]; s1 += v; s2 += v * v; }
        float mu = s1 * (1.f / 64.f);
        float var = s2 * (1.f / 64.f) - mu * mu;
        float r = rsqrtf(var + 1e-5f);
#pragma unroll
        for (int k = 0; k < 64; k++) {
            float v = rs[t * 65 + k];
            rs[t * 65 + k] = (v - mu) * r * sg[k] + sb[k];
        }
    }
    __syncthreads();

    // dual GEMM: thread (c = t&7, rg = t>>3) -> 4 rows x 8 output-pairs
    int c = t & 7, rg = t >> 3;
    const u64* wb = ((const u64*)g_wcat) + layer * 4096 + c;
    u64 acc2[4][8];
#pragma unroll
    for (int a = 0; a < 4; a++)
#pragma unroll
        for (int b = 0; b < 8; b++) acc2[a][b] = 0ull;

    const float* arow = &rs[rg * 4 * 65];
#pragma unroll 4
    for (int k = 0; k < 64; k++) {
        u64 a2[4];
#pragma unroll
        for (int rr = 0; rr < 4; rr++) {
            float av = arow[rr * 65 + k];
            a2[rr] = pk2(av, av);
        }
        u64 w2[8];
#pragma unroll
        for (int p = 0; p < 8; p++) w2[p] = wb[k * 64 + 8 * p];
#pragma unroll
        for (int rr = 0; rr < 4; rr++)
#pragma unroll
            for (int p = 0; p < 8; p++) fma2(acc2[rr][p], a2[rr], w2[p]);
    }

    // epilogue: p<4 -> y outputs, p>=4 -> z outputs (+ b_rel).
    // layer 3: skip z for location nodes (never read again).
    bool wz = !(layer == 3 && (blk * 2 + 1) < NL);
    size_t rowbase = (size_t)blk * 128 + rg * 4;
#pragma unroll
    for (int rr = 0; rr < 4; rr++) {
        size_t row = rowbase + rr;
        float* yr = yout + row * 64;
        float* zr = zout + row * 64;
#pragma unroll
        for (int p = 0; p < 8; p++) {
            int j0 = 2 * (c + 8 * p);
            float lo, hi; upk2(acc2[rr][p], lo, hi);
            if (p < 4) {
                *reinterpret_cast<float2*>(yr + j0) = make_float2(lo, hi);
            } else if (wz) {
                int jj = j0 - 64;
                *reinterpret_cast<float2*>(zr + jj) =
                    make_float2(lo + brel[layer * 64 + jj],
                                hi + brel[layer * 64 + jj + 1]);
            }
        }
    }
}

// ---------------- final: gather+relu fused with p/f readout ------------------
// Block = 2 output nodes (gen or line), 256 threads.
__global__ void __launch_bounds__(256) k_final(
    const float* __restrict__ pw, const float* __restrict__ pb,
    const float* __restrict__ fw, const float* __restrict__ fb,
    float* __restrict__ pout, float* __restrict__ fout)
{
    const float* yin = g_yB;  // layer 3 (odd) wrote B
    const float* zin = g_zB;
    int t = threadIdx.x;
    int nh = t >> 7, tt = t & 127;
    int on = blockIdx.x * 2 + nh;            // 0 .. NG+NF-1
    int d = NL + on;
    size_t base = (size_t)d * ROWF + tt * 32;
    float4 acc[8];
#pragma unroll
    for (int q = 0; q < 8; q++)
        acc[q] = *reinterpret_cast<const float4*>(zin + base + q * 4);
    int beg = g_rowptr[d], end = g_rowptr[d + 1];
    for (int e = beg; e < end; e++) {
        int s = g_col[e];
        const float* yr = yin + (size_t)s * ROWF + tt * 32;
#pragma unroll
        for (int q = 0; q < 8; q++) {
            float4 v = *reinterpret_cast<const float4*>(yr + q * 4);
            acc[q].x += v.x; acc[q].y += v.y; acc[q].z += v.z; acc[q].w += v.w;
        }
    }
    bool isg = on < NG;
    const float* w = isg ? pw : fw;
    int k0 = (tt & 1) * 32;
    float s = 0.f;
#pragma unroll
    for (int q = 0; q < 8; q++) {
        s += fmaxf(acc[q].x, 0.f) * w[k0 + q * 4 + 0];
        s += fmaxf(acc[q].y, 0.f) * w[k0 + q * 4 + 1];
        s += fmaxf(acc[q].z, 0.f) * w[k0 + q * 4 + 2];
        s += fmaxf(acc[q].w, 0.f) * w[k0 + q * 4 + 3];
    }
    s += __shfl_xor_sync(0xffffffffu, s, 1);
    if ((tt & 1) == 0) {
        int b = tt >> 1;
        if (isg) pout[b * NG + on] = s + pb[0];
        else     fout[b * NF + (on - NG)] = s + fb[0];
    }
}

// ---------------- md = demand - (p @ gm^T + f @ lm^T) via sparse scatter -----
__global__ void k_mdinit(const float* __restrict__ x, const int* __restrict__ loc,
                         float* __restrict__ md) {
    int i = blockIdx.x * 256 + threadIdx.x;
    if (i < BATCH * NL) md[i] = x[(size_t)loc[i] * 7];   // feature 0 = demand
}
__global__ void k_mdscatter(const float* __restrict__ gm, const float* __restrict__ lm,
                            const float* __restrict__ p, const float* __restrict__ f,
                            float* __restrict__ md) {
    int idx = blockIdx.x * 256 + threadIdx.x;
    const int TG = NL * NG;
    if (idx < TG) {
        float v = gm[idx];
        if (v != 0.f) {
            int l = idx / NG, g = idx % NG;
            for (int b = 0; b < BATCH; b++)
                atomicAdd(&md[b * NL + l], -v * p[b * NG + g]);
        }
    } else {
        int j = idx - TG;
        if (j >= NL * NF) return;
        float v = lm[j];
        if (v != 0.f) {
            int l = j / NF, fi = j % NF;
            for (int b = 0; b < BATCH; b++)
                atomicAdd(&md[b * NL + l], -v * f[b * NF + fi]);
        }
    }
}

// -----------------------------------------------------------------------------
extern "C" void kernel_launch(void* const* d_in, const int* in_sizes, int n_in,
                              void* d_out, int out_size) {
    const float* x        = (const float*)d_in[0];
    const int*   edge     = (const int*)  d_in[1];
    const int*   loc_idx  = (const int*)  d_in[4];
    const float* enc_w    = (const float*)d_in[5];
    const float* enc_b    = (const float*)d_in[6];
    const float* ln_g     = (const float*)d_in[7];
    const float* ln_b     = (const float*)d_in[8];
    const float* w_rel    = (const float*)d_in[9];
    const float* b_rel    = (const float*)d_in[10];
    const float* w_root   = (const float*)d_in[11];
    const float* prod_w   = (const float*)d_in[12];
    const float* prod_b   = (const float*)d_in[13];
    const float* flow_w   = (const float*)d_in[14];
    const float* flow_b   = (const float*)d_in[15];
    const float* gm       = (const float*)d_in[16];
    const float* lm       = (const float*)d_in[17];

    float* out   = (float*)d_out;
    float* p_out = out;                       // [B,G]  = 32768
    float* f_out = out + 32768;               // [B,F]  = 196608
    float* md    = out + 32768 + 196608;      // [B,L]  = 131072

    const int E = 1048576;                    // B * EG
    const int* src = edge;                    // local topology = first EG entries (b=0)
    const int* dst = edge + E;

    k_wprep<<<128, 256>>>(w_rel, w_root);
    k_zero<<<22, 256>>>();
    k_hist<<<64, 256>>>(dst);
    k_scan<<<1, 1024>>>();
    k_fill<<<64, 256>>>(src, dst);

    for (int i = 0; i < NLAYER; i++)
        k_layer<<<2816, 256>>>(ln_g, ln_b, b_rel, x, enc_w, enc_b, i);

    k_final<<<1792, 256>>>(prod_w, prod_b, flow_w, flow_b, p_out, f_out);
    k_mdinit<<<512, 256>>>(x, loc_idx, md);
    k_mdscatter<<<28672, 256>>>(gm, lm, p_out, f_out, md);
}